// round 11
// baseline (speedup 1.0000x reference)
#include <cuda_runtime.h>
#include <cuda_bf16.h>
#include <cstdint>

// N = 400 nodes, E = N*(N-1) = 159600 edges, B = 32 batch.
// Output [B, E, 2] f32: out[b,e,:] = adj[i,j]!=0 ? (0,1) : (1,0),
// edge e -> (i = e/399, j = r + (r>=i)), r = e%399  (np.where(~eye) order).
//
// Measured model (fits R2/R3/R5/R7/R8 within 5%): two CONCURRENT per-SM
// write paths, STG(L1TEX) ~16 B/cyc/SM and cp.async.bulk engine ~10.5
// B/cyc/SM. R5's 12-STG/20-bulk split overloaded the bulk side (16.2k cyc);
// the balanced split is 20 STG / 12 bulk (~10.6k cyc -> ~6us).
// 148 CTAs (one per SM), per-CTA chunk 539/540 edge-pairs (0.2% skew).

#define N_NODES 400
#define N_M1    399
#define E_PAIRS 79800           // float4 elements per batch
#define BATCH   32
#define GRID_X  148
#define THREADS 512
#define CHUNK_LO 539            // 148*539 = 79772; first 28 CTAs take 540
#define REM      28
#define NB_STG  20              // batches 0..19 via STG (rate ~16 B/cyc/SM)
#define NB_BULK 12              // batches 20..31 via bulk (rate ~10.5 B/cyc/SM)
#define MAX_CNT 540

__device__ __forceinline__ float4 pair_val(const float* __restrict__ adj, int p)
{
    const int e0 = 2 * p;
    const int e1 = e0 + 1;
    int i0 = e0 / N_M1;
    int r0 = e0 - i0 * N_M1;
    int j0 = r0 + (r0 >= i0 ? 1 : 0);
    int i1 = e1 / N_M1;
    int r1 = e1 - i1 * N_M1;
    int j1 = r1 + (r1 >= i1 ? 1 : 0);
    const float t0 = (__ldg(&adj[i0 * N_NODES + j0]) != 0.0f) ? 1.0f : 0.0f;
    const float t1 = (__ldg(&adj[i1 * N_NODES + j1]) != 0.0f) ? 1.0f : 0.0f;
    return make_float4(1.0f - t0, t0, 1.0f - t1, t1);
}

__global__ __launch_bounds__(THREADS)
void edge_onehot_dual20_kernel(const float* __restrict__ adj, float4* __restrict__ out)
{
    __shared__ alignas(128) float4 buf[MAX_CNT];

    const int bid = blockIdx.x;
    const int tid = threadIdx.x;

    // Balanced contiguous chunk: first REM CTAs take CHUNK_LO+1 pairs.
    const int cnt   = CHUNK_LO + (bid < REM ? 1 : 0);
    const int start = bid * CHUNK_LO + (bid < REM ? bid : REM);

    // ---- Phase 1: compute tile once -> regs + smem mirror.
    float4 v0, v1;
    {
        const int p = start + tid;          // tid < 512 <= cnt, always active
        v0 = pair_val(adj, p);
        buf[tid] = v0;
    }
    const int idx1 = tid + THREADS;         // [512, cnt): 27 or 28 threads
    const bool has1 = (idx1 < cnt);
    if (has1) {
        v1 = pair_val(adj, start + idx1);
        buf[idx1] = v1;
    }
    __syncthreads();

    // ---- Phase 2a: async-engine path. 12 threads each broadcast the tile
    // to one batch image (batches 20..31) with their own bulk group.
    if (tid < NB_BULK) {
        asm volatile("fence.proxy.async.shared::cta;" ::: "memory");
        uint32_t smem_addr;
        asm("{ .reg .u64 t; cvta.to.shared.u64 t, %1; cvt.u32.u64 %0, t; }"
            : "=r"(smem_addr) : "l"(buf));
        const int b = NB_STG + tid;
        float4* dst = out + (size_t)b * E_PAIRS + start;
        asm volatile(
            "cp.async.bulk.global.shared::cta.bulk_group [%0], [%1], %2;"
            :: "l"(dst), "r"(smem_addr), "r"((uint32_t)(cnt * 16))
            : "memory");
        asm volatile("cp.async.bulk.commit_group;" ::: "memory");
    }

    // ---- Phase 2b: LSU path. All threads stream-store register values to
    // batches 0..19 (runs concurrently with the bulk engine).
    float4* base0 = out + start + tid;
#pragma unroll
    for (int b = 0; b < NB_STG; ++b) {
        float4* d = base0 + (size_t)b * E_PAIRS;
        __stcs(d, v0);
        if (has1) __stcs(d + THREADS, v1);
    }

    // ---- Drain bulk copies before CTA exit (smem lifetime).
    if (tid < NB_BULK) {
        asm volatile("cp.async.bulk.wait_group 0;" ::: "memory");
    }
    __syncthreads();
}

extern "C" void kernel_launch(void* const* d_in, const int* in_sizes, int n_in,
                              void* d_out, int out_size)
{
    // metadata order: inputs, weather, rel_rec, rel_send, adj_matrix
    const float* adj = (const float*)d_in[4];
    float4* out = (float4*)d_out;

    edge_onehot_dual20_kernel<<<GRID_X, THREADS>>>(adj, out);
}

// round 13
// speedup vs baseline: 1.3107x; 1.3107x over previous
#include <cuda_runtime.h>
#include <cuda_bf16.h>
#include <cstdint>

// N = 400 nodes, E = N*(N-1) = 159600 edges, B = 32 batch.
// Output [B, E, 2] f32: out[b,e,:] = adj[i,j]!=0 ? (0,1) : (1,0),
// edge e -> (i = e/399, j = r + (r>=i)), r = e%399  (np.where(~eye) order).
//
// EXACT clone of the R5 dual-path kernel (best total: 10.72us) with ONE
// change: batch split 12 STG / 20 bulk  ->  16 STG / 16 bulk.
// Model: STG(L1TEX) ~16 B/cyc/SM and bulk engine ~10.5 B/cyc/SM run
// concurrently; R5's critical path was the 20-batch bulk side; 16/16 cuts
// it 20% while STG side stays sub-critical.

#define N_NODES 400
#define N_M1    399
#define E_PAIRS 79800           // float4 elements per batch
#define BATCH   32
#define TILE_F4 532
#define N_TILES 150             // 150 * 532 = 79800
#define TILE_BYTES (TILE_F4 * 16)   // 8512
#define NB_STG  16              // batches via STG
#define NB_BULK (BATCH - NB_STG)    // 16 batches via cp.async.bulk

__global__ __launch_bounds__(256)
void edge_onehot_dual16_kernel(const float* __restrict__ adj, float4* __restrict__ out)
{
    __shared__ alignas(128) float4 buf[TILE_F4];

    const int tid = threadIdx.x;
    const int base_p = blockIdx.x * TILE_F4;

    // ---- Phase 1: compute tile once; keep values in regs AND mirror to smem.
    float4 v0, v1, v2;
    {
        const int p = base_p + tid;                 // slot 0: tid in [0,256)
        const int e0 = 2 * p, e1 = e0 + 1;
        int i0 = e0 / N_M1, r0 = e0 - i0 * N_M1;
        int j0 = r0 + (r0 >= i0 ? 1 : 0);
        int i1 = e1 / N_M1, r1 = e1 - i1 * N_M1;
        int j1 = r1 + (r1 >= i1 ? 1 : 0);
        float t0 = (__ldg(&adj[i0 * N_NODES + j0]) != 0.0f) ? 1.0f : 0.0f;
        float t1 = (__ldg(&adj[i1 * N_NODES + j1]) != 0.0f) ? 1.0f : 0.0f;
        v0 = make_float4(1.0f - t0, t0, 1.0f - t1, t1);
        buf[tid] = v0;
    }
    {
        const int idx = tid + 256;                  // slot 1: [256,512)
        const int p = base_p + idx;
        const int e0 = 2 * p, e1 = e0 + 1;
        int i0 = e0 / N_M1, r0 = e0 - i0 * N_M1;
        int j0 = r0 + (r0 >= i0 ? 1 : 0);
        int i1 = e1 / N_M1, r1 = e1 - i1 * N_M1;
        int j1 = r1 + (r1 >= i1 ? 1 : 0);
        float t0 = (__ldg(&adj[i0 * N_NODES + j0]) != 0.0f) ? 1.0f : 0.0f;
        float t1 = (__ldg(&adj[i1 * N_NODES + j1]) != 0.0f) ? 1.0f : 0.0f;
        v1 = make_float4(1.0f - t0, t0, 1.0f - t1, t1);
        buf[idx] = v1;
    }
    const bool has2 = (tid < TILE_F4 - 512);        // 20 threads: [512,532)
    if (has2) {
        const int idx = tid + 512;
        const int p = base_p + idx;
        const int e0 = 2 * p, e1 = e0 + 1;
        int i0 = e0 / N_M1, r0 = e0 - i0 * N_M1;
        int j0 = r0 + (r0 >= i0 ? 1 : 0);
        int i1 = e1 / N_M1, r1 = e1 - i1 * N_M1;
        int j1 = r1 + (r1 >= i1 ? 1 : 0);
        float t0 = (__ldg(&adj[i0 * N_NODES + j0]) != 0.0f) ? 1.0f : 0.0f;
        float t1 = (__ldg(&adj[i1 * N_NODES + j1]) != 0.0f) ? 1.0f : 0.0f;
        v2 = make_float4(1.0f - t0, t0, 1.0f - t1, t1);
        buf[idx] = v2;
    }

    __syncthreads();

    // ---- Phase 2a: async-engine path. Threads 0..NB_BULK-1 each broadcast
    // the smem tile to one batch image with their own bulk group.
    if (tid < NB_BULK) {
        asm volatile("fence.proxy.async.shared::cta;" ::: "memory");
        uint32_t smem_addr;
        asm("{ .reg .u64 t; cvta.to.shared.u64 t, %1; cvt.u32.u64 %0, t; }"
            : "=r"(smem_addr) : "l"(buf));
        const int b = NB_STG + tid;
        float4* dst = out + (size_t)b * E_PAIRS + base_p;
        asm volatile(
            "cp.async.bulk.global.shared::cta.bulk_group [%0], [%1], %2;"
            :: "l"(dst), "r"(smem_addr), "r"((uint32_t)TILE_BYTES)
            : "memory");
        asm volatile("cp.async.bulk.commit_group;" ::: "memory");
    }

    // ---- Phase 2b: LSU path. All threads store their register values to
    // batches [0, NB_STG) with streaming STG.128.
    float4* base0 = out + base_p + tid;
#pragma unroll
    for (int b = 0; b < NB_STG; ++b) {
        float4* d = base0 + (size_t)b * E_PAIRS;
        __stcs(d, v0);
        __stcs(d + 256, v1);
        if (has2) __stcs(d + 512, v2);
    }

    // ---- Drain bulk copies before CTA exit (smem lifetime).
    if (tid < NB_BULK) {
        asm volatile("cp.async.bulk.wait_group 0;" ::: "memory");
    }
    __syncthreads();
}

extern "C" void kernel_launch(void* const* d_in, const int* in_sizes, int n_in,
                              void* d_out, int out_size)
{
    // metadata order: inputs, weather, rel_rec, rel_send, adj_matrix
    const float* adj = (const float*)d_in[4];
    float4* out = (float4*)d_out;

    edge_onehot_dual16_kernel<<<N_TILES, 256>>>(adj, out);
}

// round 14
// speedup vs baseline: 1.3528x; 1.0321x over previous
#include <cuda_runtime.h>
#include <cuda_bf16.h>
#include <cstdint>

// N = 400 nodes, E = N*(N-1) = 159600 edges, B = 32 batch.
// Output [B, E, 2] f32: out[b,e,:] = adj[i,j]!=0 ? (0,1) : (1,0),
// edge e -> (i = e/399, j = r + (r>=i)), r = e%399  (np.where(~eye) order).
//
// CONVERGED: 9 structural variants (STG.128/.256, plain/.cs, bulk-only,
// dual splits 12/20, 16/16, 20/12, occupancy 10-72%) all pin at
// ~2400 B/cyc chip-wide write throughput -> ~9.5-9.9us for 40.85MB.
// The limiter is the shared L2/LTS WRITE port (~half the 6300 B/cyc read
// cap), not issue rate, wavefronts, balance, or path choice.
// This is the best-measured-total config (R5: 150 CTAs x 256 thr, 12 batches
// via STG + 20 via per-thread cp.async.bulk), with plain STG.128 (the
// fastest-measured store flavor).

#define N_NODES 400
#define N_M1    399
#define E_PAIRS 79800           // float4 elements per batch
#define BATCH   32
#define TILE_F4 532
#define N_TILES 150             // 150 * 532 = 79800
#define TILE_BYTES (TILE_F4 * 16)   // 8512
#define NB_STG  12              // batches via STG
#define NB_BULK (BATCH - NB_STG)    // 20 batches via cp.async.bulk

__device__ __forceinline__ float4 pair_val(const float* __restrict__ adj, int p)
{
    const int e0 = 2 * p;
    const int e1 = e0 + 1;
    int i0 = e0 / N_M1;
    int r0 = e0 - i0 * N_M1;
    int j0 = r0 + (r0 >= i0 ? 1 : 0);
    int i1 = e1 / N_M1;
    int r1 = e1 - i1 * N_M1;
    int j1 = r1 + (r1 >= i1 ? 1 : 0);
    const float t0 = (__ldg(&adj[i0 * N_NODES + j0]) != 0.0f) ? 1.0f : 0.0f;
    const float t1 = (__ldg(&adj[i1 * N_NODES + j1]) != 0.0f) ? 1.0f : 0.0f;
    return make_float4(1.0f - t0, t0, 1.0f - t1, t1);
}

__global__ __launch_bounds__(256)
void edge_onehot_final_kernel(const float* __restrict__ adj, float4* __restrict__ out)
{
    __shared__ alignas(128) float4 buf[TILE_F4];

    const int tid = threadIdx.x;
    const int base_p = blockIdx.x * TILE_F4;

    // ---- Phase 1: compute tile once; keep values in regs AND mirror to smem.
    float4 v0, v1, v2;
    {
        v0 = pair_val(adj, base_p + tid);           // slot 0: [0,256)
        buf[tid] = v0;
    }
    {
        v1 = pair_val(adj, base_p + tid + 256);     // slot 1: [256,512)
        buf[tid + 256] = v1;
    }
    const bool has2 = (tid < TILE_F4 - 512);        // 20 threads: [512,532)
    if (has2) {
        v2 = pair_val(adj, base_p + tid + 512);
        buf[tid + 512] = v2;
    }

    __syncthreads();

    // ---- Phase 2a: async-engine path. Threads 0..NB_BULK-1 each broadcast
    // the smem tile to one batch image with their own bulk group.
    if (tid < NB_BULK) {
        asm volatile("fence.proxy.async.shared::cta;" ::: "memory");
        uint32_t smem_addr;
        asm("{ .reg .u64 t; cvta.to.shared.u64 t, %1; cvt.u32.u64 %0, t; }"
            : "=r"(smem_addr) : "l"(buf));
        const int b = NB_STG + tid;
        float4* dst = out + (size_t)b * E_PAIRS + base_p;
        asm volatile(
            "cp.async.bulk.global.shared::cta.bulk_group [%0], [%1], %2;"
            :: "l"(dst), "r"(smem_addr), "r"((uint32_t)TILE_BYTES)
            : "memory");
        asm volatile("cp.async.bulk.commit_group;" ::: "memory");
    }

    // ---- Phase 2b: LSU path. All threads store register values to
    // batches [0, NB_STG) with plain coalesced STG.128.
    float4* base0 = out + base_p + tid;
#pragma unroll
    for (int b = 0; b < NB_STG; ++b) {
        float4* d = base0 + (size_t)b * E_PAIRS;
        d[0]   = v0;
        d[256] = v1;
        if (has2) d[512] = v2;
    }

    // ---- Drain bulk copies before CTA exit (smem lifetime).
    if (tid < NB_BULK) {
        asm volatile("cp.async.bulk.wait_group 0;" ::: "memory");
    }
    __syncthreads();
}

extern "C" void kernel_launch(void* const* d_in, const int* in_sizes, int n_in,
                              void* d_out, int out_size)
{
    // metadata order: inputs, weather, rel_rec, rel_send, adj_matrix
    const float* adj = (const float*)d_in[4];
    float4* out = (float4*)d_out;

    edge_onehot_final_kernel<<<N_TILES, 256>>>(adj, out);
}